// round 4
// baseline (speedup 1.0000x reference)
#include <cuda_runtime.h>
#include <math.h>

// ---------------------------------------------------------------------------
// Problem constants (shapes fixed by setup_inputs)
// ---------------------------------------------------------------------------
#define B_SZ   2
#define C_SZ   128
#define S_SZ   262144          // 64*64*64 voxels per (b,c)
#define NPAIR  (B_SZ * C_SZ)   // 256
#define NCHUNK 8
#define GBASES 8               // GRID_SIZE + SPLINE_ORDER = 5 + 3

// Scratch (no device allocation allowed)
__device__ float g_psum[NPAIR * NCHUNK];
__device__ float g_pmax[NPAIR * NCHUNK];
__device__ float g_att[NPAIR];   // sigmoid channel attention per (b,c)
__device__ float g_wc[NPAIR];    // att * conv_w  per (b,c)

// ---------------------------------------------------------------------------
// Cox-de Boor B-spline bases, k=3, grid = arange(-3,9)*0.4 - 1  (12 knots).
// Uniform grid -> FDIV replaced by multiply with compile-time reciprocals.
// ---------------------------------------------------------------------------
__device__ __forceinline__ void bspline8(float x, float* __restrict__ out) {
    float grid[12];
#pragma unroll
    for (int i = 0; i < 12; i++) grid[i] = (float)(i - 3) * 0.4f - 1.0f;
    float b[11];
#pragma unroll
    for (int j = 0; j < 11; j++)
        b[j] = (x >= grid[j] && x < grid[j + 1]) ? 1.0f : 0.0f;
    const float inv[3] = {2.5f, 1.25f, 1.0f / 1.2f};
#pragma unroll
    for (int j = 1; j <= 3; j++) {
        const float r = inv[j - 1];
#pragma unroll
        for (int m = 0; m < 11; m++) {
            if (m < 11 - j) {
                b[m] = (x - grid[m]) * r * b[m]
                     + (grid[m + j + 1] - x) * r * b[m + 1];
            }
        }
    }
#pragma unroll
    for (int g = 0; g < GBASES; g++) out[g] = b[g];
}

__device__ __forceinline__ float siluf(float v) { return v * (1.0f / (1.0f + __expf(-v))); }
__device__ __forceinline__ float sigmoidf_(float v) { return 1.0f / (1.0f + __expf(-v)); }

// 1->1 spatial KAN: sigmoid( silu(y)*kb + sum_g base_g(y)*sw[g] )
__device__ __forceinline__ float spatial_att(float y, float kb,
                                             const float* __restrict__ sw) {
    float bas[GBASES];
    bspline8(y, bas);
    float acc = siluf(y) * kb;
#pragma unroll
    for (int g = 0; g < GBASES; g++) acc += bas[g] * sw[g];
    return sigmoidf_(acc);
}

// ---------------------------------------------------------------------------
// Kernel 1: per-(b,c) partial sum/max pooling. ~84% DRAM — leave as is.
// ---------------------------------------------------------------------------
__global__ void __launch_bounds__(256) pool_kernel(const float* __restrict__ x) {
    const int pair  = blockIdx.x >> 3;
    const int chunk = blockIdx.x & 7;
    const float4* p = (const float4*)(x + (size_t)pair * S_SZ + (size_t)chunk * (S_SZ / NCHUNK));

    float s = 0.0f, m = -3.4e38f;
#pragma unroll 4
    for (int it = 0; it < (S_SZ / NCHUNK / 4) / 256; it++) {
        float4 v = __ldcs(&p[it * 256 + threadIdx.x]);
        s += (v.x + v.y) + (v.z + v.w);
        m = fmaxf(m, fmaxf(fmaxf(v.x, v.y), fmaxf(v.z, v.w)));
    }
#pragma unroll
    for (int o = 16; o; o >>= 1) {
        s += __shfl_xor_sync(0xffffffffu, s, o);
        m = fmaxf(m, __shfl_xor_sync(0xffffffffu, m, o));
    }
    __shared__ float ss[8], sm[8];
    const int w = threadIdx.x >> 5, l = threadIdx.x & 31;
    if (l == 0) { ss[w] = s; sm[w] = m; }
    __syncthreads();
    if (threadIdx.x == 0) {
        float ts = 0.0f, tm = -3.4e38f;
#pragma unroll
        for (int i = 0; i < 8; i++) { ts += ss[i]; tm = fmaxf(tm, sm[i]); }
        g_psum[blockIdx.x] = ts;
        g_pmax[blockIdx.x] = tm;
    }
}

// ---------------------------------------------------------------------------
// Kernel 2: channel attention MLP (tiny). 1 block, 256 threads.
// ---------------------------------------------------------------------------
__global__ void __launch_bounds__(256) att_kernel(
    const float* __restrict__ ck1b,   // [8,128]
    const float* __restrict__ ck1s,   // [8,128,8]
    const float* __restrict__ ck2b,   // [128,8]
    const float* __restrict__ ck2s,   // [128,8,8]
    const float* __restrict__ convw)  // [128]
{
    __shared__ float s_val[512];            // [src(2)][pair(256)]
    __shared__ float s_silu[512];
    __shared__ float s_bas[512][GBASES];
    __shared__ float s_h1silu[32];          // [src][b][r]
    __shared__ float s_h1bas[32][GBASES];
    __shared__ float s_out[512];

    const int tid = threadIdx.x;

    // phase 0: reduce pooling partials
    {
        float ts = 0.0f, tm = -3.4e38f;
#pragma unroll
        for (int k = 0; k < NCHUNK; k++) {
            ts += g_psum[tid * NCHUNK + k];
            tm = fmaxf(tm, g_pmax[tid * NCHUNK + k]);
        }
        s_val[tid]       = ts * (1.0f / (float)S_SZ);  // y_avg
        s_val[256 + tid] = tm;                          // y_max
    }
    __syncthreads();

    // phase 1: silu + bases for all 512 pooled values
    for (int q = tid; q < 512; q += 256) {
        float v = s_val[q];
        s_silu[q] = siluf(v);
        bspline8(v, s_bas[q]);
    }
    __syncthreads();

    // phase 2: layer 1 -> h1 (32 tasks: src x b x r)
    if (tid < 32) {
        const int src = tid >> 4, b = (tid >> 3) & 1, r = tid & 7;
        const int base = src * 256 + b * 128;
        float acc = 0.0f;
        for (int i = 0; i < C_SZ; i++) {
            const int q = base + i;
            acc += s_silu[q] * ck1b[r * C_SZ + i];
            const float* sw = ck1s + (r * C_SZ + i) * GBASES;
#pragma unroll
            for (int g = 0; g < GBASES; g++) acc += s_bas[q][g] * sw[g];
        }
        const float hv = fmaxf(acc, 0.0f);
        s_h1silu[tid] = siluf(hv);
        bspline8(hv, s_h1bas[tid]);
    }
    __syncthreads();

    // phase 3: layer 2 (512 tasks: src x b x c)
    for (int q = tid; q < 512; q += 256) {
        const int src = q >> 8, b = (q >> 7) & 1, c = q & 127;
        float acc = 0.0f;
#pragma unroll
        for (int r = 0; r < 8; r++) {
            const int hq = src * 16 + b * 8 + r;
            acc += s_h1silu[hq] * ck2b[c * 8 + r];
            const float* sw = ck2s + (c * 8 + r) * GBASES;
#pragma unroll
            for (int g = 0; g < GBASES; g++) acc += s_h1bas[hq][g] * sw[g];
        }
        s_out[q] = acc;
    }
    __syncthreads();

    // phase 4: combine avg+max, sigmoid, and fold in conv_w
    {
        const float a = sigmoidf_(s_out[tid] + s_out[256 + tid]);
        g_att[tid] = a;
        g_wc[tid]  = a * convw[tid & 127];
    }
}

// ---------------------------------------------------------------------------
// Kernel 3: fused spatial pass — ONE barrier, no serial middle phase.
// Tile = 64 voxels x 128 channels. 256 threads: s4 = tid&15 (float4 lane),
// cp = tid>>4 (channel-octet). Each thread keeps its 8 channel-scaled float4
// in registers; after the single barrier EVERY thread reduces the 8 wred
// partials for its own float4 and computes the 1->1 KAN spline redundantly
// (4 splines/thread, fma pipe was at 4.6% — free), then stores immediately.
// ---------------------------------------------------------------------------
__global__ void __launch_bounds__(256) fused_kernel(
    const float* __restrict__ x,
    const float* __restrict__ skb,   // [1]
    const float* __restrict__ sks,   // [8]
    float* __restrict__ out)
{
    __shared__ float4 wred[8][16];                // per-(cp-pair) partial y_spatial

    const int b    = blockIdx.x >> 12;            // 4096 tiles per batch
    const int tile = blockIdx.x & 4095;
    const int s4   = threadIdx.x & 15;
    const int cp   = threadIdx.x >> 4;

    const size_t sbase4 = (size_t)tile * 16;      // float4 offset in plane
    const float4* xp = (const float4*)x;
    float4* op = (float4*)out;

    float4 va[8];                                  // x * channel_att (registers)
    float4 ws = make_float4(0.f, 0.f, 0.f, 0.f);
    const int cbase = cp * 8;
#pragma unroll
    for (int k = 0; k < 8; k++) {
        const int pair = b * C_SZ + cbase + k;
        const float4 v = __ldcs(&xp[((size_t)pair << 16) + sbase4 + (size_t)s4]);
        const float a  = g_att[pair];
        const float wc = g_wc[pair];
        va[k] = make_float4(v.x * a, v.y * a, v.z * a, v.w * a);
        ws.x += v.x * wc; ws.y += v.y * wc; ws.z += v.z * wc; ws.w += v.w * wc;
    }
    // pre-reduce cp pairs (tid, tid^16 share a warp, same s4)
    ws.x += __shfl_xor_sync(0xffffffffu, ws.x, 16);
    ws.y += __shfl_xor_sync(0xffffffffu, ws.y, 16);
    ws.z += __shfl_xor_sync(0xffffffffu, ws.z, 16);
    ws.w += __shfl_xor_sync(0xffffffffu, ws.w, 16);
    if ((cp & 1) == 0) wred[cp >> 1][s4] = ws;
    __syncthreads();

    // every thread: finish the 8-way reduction for its own float4 of voxels
    float4 y = wred[0][s4];
#pragma unroll
    for (int p = 1; p < 8; p++) {
        const float4 u = wred[p][s4];
        y.x += u.x; y.y += u.y; y.z += u.z; y.w += u.w;
    }

    const float kb = skb[0];
    float sw[GBASES];
#pragma unroll
    for (int g = 0; g < GBASES; g++) sw[g] = sks[g];

    float4 sa;
    sa.x = spatial_att(y.x, kb, sw);
    sa.y = spatial_att(y.y, kb, sw);
    sa.z = spatial_att(y.z, kb, sw);
    sa.w = spatial_att(y.w, kb, sw);

#pragma unroll
    for (int k = 0; k < 8; k++) {
        const int pair = b * C_SZ + cbase + k;
        __stcs(&op[((size_t)pair << 16) + sbase4 + (size_t)s4],
               make_float4(va[k].x * sa.x, va[k].y * sa.y,
                           va[k].z * sa.z, va[k].w * sa.w));
    }
}

// ---------------------------------------------------------------------------
// Launch
// ---------------------------------------------------------------------------
extern "C" void kernel_launch(void* const* d_in, const int* in_sizes, int n_in,
                              void* d_out, int out_size) {
    const float* x     = (const float*)d_in[0];
    const float* ck1b  = (const float*)d_in[1];
    const float* ck1s  = (const float*)d_in[2];
    const float* ck2b  = (const float*)d_in[3];
    const float* ck2s  = (const float*)d_in[4];
    const float* convw = (const float*)d_in[5];
    const float* skb   = (const float*)d_in[6];
    const float* sks   = (const float*)d_in[7];
    float* out = (float*)d_out;

    pool_kernel<<<NPAIR * NCHUNK, 256>>>(x);
    att_kernel<<<1, 256>>>(ck1b, ck1s, ck2b, ck2s, convw);
    fused_kernel<<<B_SZ * (S_SZ / 64), 256>>>(x, skb, sks, out);
}

// round 5
// speedup vs baseline: 1.0804x; 1.0804x over previous
#include <cuda_runtime.h>
#include <math.h>

// ---------------------------------------------------------------------------
// Problem constants (shapes fixed by setup_inputs)
// ---------------------------------------------------------------------------
#define B_SZ   2
#define C_SZ   128
#define S_SZ   262144          // 64*64*64 voxels per (b,c)
#define NPAIR  (B_SZ * C_SZ)   // 256
#define NCHUNK 8
#define GBASES 8               // GRID_SIZE + SPLINE_ORDER = 5 + 3

// Scratch (no device allocation allowed)
__device__ float g_psum[NPAIR * NCHUNK];
__device__ float g_pmax[NPAIR * NCHUNK];
__device__ float g_att[NPAIR];   // sigmoid channel attention per (b,c)
__device__ float g_wc[NPAIR];    // att * conv_w  per (b,c)

// ---------------------------------------------------------------------------
// Cox-de Boor B-spline bases, k=3, grid = arange(-3,9)*0.4 - 1  (12 knots).
// Uniform grid -> FDIV replaced by multiply with compile-time reciprocals.
// ---------------------------------------------------------------------------
__device__ __forceinline__ void bspline8(float x, float* __restrict__ out) {
    float grid[12];
#pragma unroll
    for (int i = 0; i < 12; i++) grid[i] = (float)(i - 3) * 0.4f - 1.0f;
    float b[11];
#pragma unroll
    for (int j = 0; j < 11; j++)
        b[j] = (x >= grid[j] && x < grid[j + 1]) ? 1.0f : 0.0f;
    const float inv[3] = {2.5f, 1.25f, 1.0f / 1.2f};
#pragma unroll
    for (int j = 1; j <= 3; j++) {
        const float r = inv[j - 1];
#pragma unroll
        for (int m = 0; m < 11; m++) {
            if (m < 11 - j) {
                b[m] = (x - grid[m]) * r * b[m]
                     + (grid[m + j + 1] - x) * r * b[m + 1];
            }
        }
    }
#pragma unroll
    for (int g = 0; g < GBASES; g++) out[g] = b[g];
}

__device__ __forceinline__ float siluf(float v) { return v * (1.0f / (1.0f + __expf(-v))); }
__device__ __forceinline__ float sigmoidf_(float v) { return 1.0f / (1.0f + __expf(-v)); }

// ---------------------------------------------------------------------------
// Kernel 1: per-(b,c) partial sum/max pooling. ~84% DRAM — leave as is.
// ---------------------------------------------------------------------------
__global__ void __launch_bounds__(256) pool_kernel(const float* __restrict__ x) {
    const int pair  = blockIdx.x >> 3;
    const int chunk = blockIdx.x & 7;
    const float4* p = (const float4*)(x + (size_t)pair * S_SZ + (size_t)chunk * (S_SZ / NCHUNK));

    float s = 0.0f, m = -3.4e38f;
#pragma unroll 4
    for (int it = 0; it < (S_SZ / NCHUNK / 4) / 256; it++) {
        float4 v = __ldcs(&p[it * 256 + threadIdx.x]);
        s += (v.x + v.y) + (v.z + v.w);
        m = fmaxf(m, fmaxf(fmaxf(v.x, v.y), fmaxf(v.z, v.w)));
    }
#pragma unroll
    for (int o = 16; o; o >>= 1) {
        s += __shfl_xor_sync(0xffffffffu, s, o);
        m = fmaxf(m, __shfl_xor_sync(0xffffffffu, m, o));
    }
    __shared__ float ss[8], sm[8];
    const int w = threadIdx.x >> 5, l = threadIdx.x & 31;
    if (l == 0) { ss[w] = s; sm[w] = m; }
    __syncthreads();
    if (threadIdx.x == 0) {
        float ts = 0.0f, tm = -3.4e38f;
#pragma unroll
        for (int i = 0; i < 8; i++) { ts += ss[i]; tm = fmaxf(tm, sm[i]); }
        g_psum[blockIdx.x] = ts;
        g_pmax[blockIdx.x] = tm;
    }
}

// ---------------------------------------------------------------------------
// Kernel 2: channel attention MLP (tiny). 1 block, 256 threads.
// ---------------------------------------------------------------------------
__global__ void __launch_bounds__(256) att_kernel(
    const float* __restrict__ ck1b,   // [8,128]
    const float* __restrict__ ck1s,   // [8,128,8]
    const float* __restrict__ ck2b,   // [128,8]
    const float* __restrict__ ck2s,   // [128,8,8]
    const float* __restrict__ convw)  // [128]
{
    __shared__ float s_val[512];            // [src(2)][pair(256)]
    __shared__ float s_silu[512];
    __shared__ float s_bas[512][GBASES];
    __shared__ float s_h1silu[32];          // [src][b][r]
    __shared__ float s_h1bas[32][GBASES];
    __shared__ float s_out[512];

    const int tid = threadIdx.x;

    // phase 0: reduce pooling partials
    {
        float ts = 0.0f, tm = -3.4e38f;
#pragma unroll
        for (int k = 0; k < NCHUNK; k++) {
            ts += g_psum[tid * NCHUNK + k];
            tm = fmaxf(tm, g_pmax[tid * NCHUNK + k]);
        }
        s_val[tid]       = ts * (1.0f / (float)S_SZ);  // y_avg
        s_val[256 + tid] = tm;                          // y_max
    }
    __syncthreads();

    // phase 1: silu + bases for all 512 pooled values
    for (int q = tid; q < 512; q += 256) {
        float v = s_val[q];
        s_silu[q] = siluf(v);
        bspline8(v, s_bas[q]);
    }
    __syncthreads();

    // phase 2: layer 1 -> h1 (32 tasks: src x b x r)
    if (tid < 32) {
        const int src = tid >> 4, b = (tid >> 3) & 1, r = tid & 7;
        const int base = src * 256 + b * 128;
        float acc = 0.0f;
        for (int i = 0; i < C_SZ; i++) {
            const int q = base + i;
            acc += s_silu[q] * ck1b[r * C_SZ + i];
            const float* sw = ck1s + (r * C_SZ + i) * GBASES;
#pragma unroll
            for (int g = 0; g < GBASES; g++) acc += s_bas[q][g] * sw[g];
        }
        const float hv = fmaxf(acc, 0.0f);
        s_h1silu[tid] = siluf(hv);
        bspline8(hv, s_h1bas[tid]);
    }
    __syncthreads();

    // phase 3: layer 2 (512 tasks: src x b x c)
    for (int q = tid; q < 512; q += 256) {
        const int src = q >> 8, b = (q >> 7) & 1, c = q & 127;
        float acc = 0.0f;
#pragma unroll
        for (int r = 0; r < 8; r++) {
            const int hq = src * 16 + b * 8 + r;
            acc += s_h1silu[hq] * ck2b[c * 8 + r];
            const float* sw = ck2s + (c * 8 + r) * GBASES;
#pragma unroll
            for (int g = 0; g < GBASES; g++) acc += s_h1bas[hq][g] * sw[g];
        }
        s_out[q] = acc;
    }
    __syncthreads();

    // phase 4: combine avg+max, sigmoid, and fold in conv_w
    {
        const float a = sigmoidf_(s_out[tid] + s_out[256 + tid]);
        g_att[tid] = a;
        g_wc[tid]  = a * convw[tid & 127];
    }
}

// ---------------------------------------------------------------------------
// Kernel 3: fused spatial pass — R3 dataflow, HIGHER OCCUPANCY.
// Tile = 64 voxels x 128 channels, 512 threads: s4 = tid&15 (float4 lane),
// cp = tid>>4 in [0,32) with 4 channels each (va[4] -> ~40 regs, more
// resident warps per SM to cover the barrier windows). Reduction: shfl over
// cp-pairs (tid^16, same warp) -> 16 partials in shared -> 64-thread finish
// + one spline per voxel -> broadcast -> stores.
// ---------------------------------------------------------------------------
__global__ void __launch_bounds__(512) fused_kernel(
    const float* __restrict__ x,
    const float* __restrict__ skb,   // [1]
    const float* __restrict__ sks,   // [8]
    float* __restrict__ out)
{
    __shared__ float4 wred[16][16];               // per-(cp-pair) partial y_spatial
    __shared__ __align__(16) float satts[64];     // per-voxel spatial attention

    const int b    = blockIdx.x >> 12;            // 4096 tiles per batch
    const int tile = blockIdx.x & 4095;
    const int s4   = threadIdx.x & 15;
    const int cp   = threadIdx.x >> 4;            // 0..31, 4 channels each

    const size_t sbase4 = (size_t)tile * 16;      // float4 offset in plane
    const float4* xp = (const float4*)x;
    float4* op = (float4*)out;

    float4 va[4];                                  // x * channel_att (registers)
    float4 ws = make_float4(0.f, 0.f, 0.f, 0.f);
    const int cbase = cp * 4;
#pragma unroll
    for (int k = 0; k < 4; k++) {
        const int pair = b * C_SZ + cbase + k;
        const float4 v = __ldcs(&xp[((size_t)pair << 16) + sbase4 + (size_t)s4]);
        const float a  = g_att[pair];
        const float wc = g_wc[pair];
        va[k] = make_float4(v.x * a, v.y * a, v.z * a, v.w * a);
        ws.x += v.x * wc; ws.y += v.y * wc; ws.z += v.z * wc; ws.w += v.w * wc;
    }
    // pre-reduce cp pairs: tid and tid^16 share a warp and the same s4
    ws.x += __shfl_xor_sync(0xffffffffu, ws.x, 16);
    ws.y += __shfl_xor_sync(0xffffffffu, ws.y, 16);
    ws.z += __shfl_xor_sync(0xffffffffu, ws.z, 16);
    ws.w += __shfl_xor_sync(0xffffffffu, ws.w, 16);
    if ((cp & 1) == 0) wred[cp >> 1][s4] = ws;
    __syncthreads();

    // 64 threads: each reduces one voxel scalar, then does the 1->1 KAN.
    if (threadIdx.x < 64) {
        const int v   = threadIdx.x;
        const int s4i = v >> 2;
        const int j   = v & 3;
        const float* wf = (const float*)wred;
        float y = 0.0f;
#pragma unroll
        for (int p = 0; p < 16; p++) y += wf[(p * 16 + s4i) * 4 + j];

        float bas[GBASES];
        bspline8(y, bas);
        float acc = siluf(y) * skb[0];
#pragma unroll
        for (int g = 0; g < GBASES; g++) acc += bas[g] * sks[g];
        satts[v] = sigmoidf_(acc);
    }
    __syncthreads();

    const float4 sa = ((const float4*)satts)[s4];
#pragma unroll
    for (int k = 0; k < 4; k++) {
        const int pair = b * C_SZ + cbase + k;
        __stcs(&op[((size_t)pair << 16) + sbase4 + (size_t)s4],
               make_float4(va[k].x * sa.x, va[k].y * sa.y,
                           va[k].z * sa.z, va[k].w * sa.w));
    }
}

// ---------------------------------------------------------------------------
// Launch
// ---------------------------------------------------------------------------
extern "C" void kernel_launch(void* const* d_in, const int* in_sizes, int n_in,
                              void* d_out, int out_size) {
    const float* x     = (const float*)d_in[0];
    const float* ck1b  = (const float*)d_in[1];
    const float* ck1s  = (const float*)d_in[2];
    const float* ck2b  = (const float*)d_in[3];
    const float* ck2s  = (const float*)d_in[4];
    const float* convw = (const float*)d_in[5];
    const float* skb   = (const float*)d_in[6];
    const float* sks   = (const float*)d_in[7];
    float* out = (float*)d_out;

    pool_kernel<<<NPAIR * NCHUNK, 256>>>(x);
    att_kernel<<<1, 256>>>(ck1b, ck1s, ck2b, ck2s, convw);
    fused_kernel<<<B_SZ * (S_SZ / 64), 512>>>(x, skb, sks, out);
}